// round 10
// baseline (speedup 1.0000x reference)
#include <cuda_runtime.h>
#include <cstdint>
#include <math.h>

#define BATCH 4
#define SEQ   4096
#define DIM   512
#define ROWS  (BATCH*SEQ)   // 16384
#define NCHUNK 32
#define CHUNK  128          // SEQ / NCHUNK
#define CLSZ   8            // cluster size for chain
#define BPC   2             // batches per cluster (interleaved)

// ---- scratch (no cudaMalloc allowed) ----
__device__ float g_R[ROWS*DIM];
__device__ float g_G[ROWS*DIM];
__device__ float g_C[ROWS*DIM];
__device__ float g_S[ROWS*DIM];
__device__ float g_cf[BATCH*NCHUNK*DIM];
__device__ float g_cp[BATCH*NCHUNK*DIM];

// ---------------- helpers ----------------
__device__ __forceinline__ uint32_t smem_u32(const void* p) {
    return (uint32_t)__cvta_generic_to_shared(p);
}
__device__ __forceinline__ void fma2(unsigned long long& d, unsigned long long a, unsigned long long b) {
    asm("fma.rn.f32x2 %0, %1, %2, %0;" : "+l"(d) : "l"(a), "l"(b));
}
__device__ __forceinline__ unsigned long long dupf(float a) {
    unsigned long long r;
    asm("mov.b64 %0, {%1, %1};" : "=l"(r) : "f"(a));
    return r;
}
__device__ __forceinline__ void unpack2(unsigned long long v, float& lo, float& hi) {
    asm("mov.b64 {%0, %1}, %2;" : "=f"(lo), "=f"(hi) : "l"(v));
}
__device__ __forceinline__ void mbar_init(uint32_t addr, uint32_t cnt) {
    asm volatile("mbarrier.init.shared.b64 [%0], %1;" :: "r"(addr), "r"(cnt) : "memory");
}
__device__ __forceinline__ void mbar_expect_tx(uint32_t addr, uint32_t bytes) {
    asm volatile("mbarrier.arrive.expect_tx.shared.b64 _, [%0], %1;" :: "r"(addr), "r"(bytes) : "memory");
}
__device__ __forceinline__ void st_async_u32(uint32_t raddr, uint32_t val, uint32_t rmbar) {
    asm volatile("st.async.weak.shared::cluster.mbarrier::complete_tx::bytes.b32 [%0], %1, [%2];"
                 :: "r"(raddr), "r"(val), "r"(rmbar) : "memory");
}
__device__ __forceinline__ void mbar_wait(uint32_t addr, uint32_t parity) {
    uint32_t done;
    asm volatile("{\n\t.reg .pred P;\n\t"
        "mbarrier.try_wait.parity.acquire.cta.shared::cta.b64 P, [%1], %2, 0x989680;\n\t"
        "selp.b32 %0, 1, 0, P;\n\t}"
        : "=r"(done) : "r"(addr), "r"(parity) : "memory");
    while (!done) {
        asm volatile("{\n\t.reg .pred P;\n\t"
            "mbarrier.try_wait.parity.acquire.cta.shared::cta.b64 P, [%1], %2, 0x989680;\n\t"
            "selp.b32 %0, 1, 0, P;\n\t}"
            : "=r"(done) : "r"(addr), "r"(parity) : "memory");
    }
}
#define CLUSTER_SYNC() do { \
    asm volatile("barrier.cluster.arrive.aligned;" ::: "memory"); \
    asm volatile("barrier.cluster.wait.aligned;"   ::: "memory"); } while (0)

// ============================================================
// Chunked linear scan for r
// ============================================================
__global__ void scan_local(const float* __restrict__ k, const float* __restrict__ v,
                           const float* __restrict__ decay, int store)
{
    int g = blockIdx.x*blockDim.x + threadIdx.x;
    int d = g % DIM;
    int c = (g / DIM) % NCHUNK;
    int b = g / (DIM*NCHUNK);
    float dec = decay[d >> 6];
    float r = store ? g_cp[g] : 0.0f;
    size_t base = ((size_t)b*SEQ + (size_t)c*CHUNK)*DIM + d;
    #pragma unroll 4
    for (int u = 0; u < CHUNK; u++) {
        size_t off = base + (size_t)u*DIM;
        r = fmaf(dec, r, k[off]*v[off]);
        if (store) g_R[off] = r;
    }
    if (!store) g_cf[g] = r;
}

__global__ void scan_prefix(const float* __restrict__ decay)
{
    int g = blockIdx.x*blockDim.x + threadIdx.x;
    int d = g % DIM;
    int b = g / DIM;
    float dec = decay[d >> 6];
    float dp = powf(dec, (float)CHUNK);
    float p = 0.0f;
    for (int c = 0; c < NCHUNK; c++) {
        int idx = (b*NCHUNK + c)*DIM + d;
        g_cp[idx] = p;
        p = g_cf[idx] + dp*p;
    }
}

// ============================================================
// GEMM: Y[M,512] = act(X[M,512] @ W[512,512]^T + bias), f32x2 inner
// ============================================================
__global__ __launch_bounds__(256)
void gemm_kernel(const float* __restrict__ X, const float* __restrict__ W,
                 const float* __restrict__ bias, float* __restrict__ Y, int act)
{
    __shared__ __align__(16) float Xs[16][132];
    __shared__ __align__(16) float Ws[16][132];
    const int K = DIM;
    int tid  = threadIdx.x;
    int m0   = blockIdx.y * 128;
    int n0   = blockIdx.x * 128;
    int rowc = (tid >> 4) << 3;
    int colc = (tid & 15) << 3;

    unsigned long long acc2[8][4];
    #pragma unroll
    for (int i = 0; i < 8; i++)
        #pragma unroll
        for (int j = 0; j < 4; j++) acc2[i][j] = 0ull;

    for (int kt = 0; kt < K; kt += 16) {
        #pragma unroll
        for (int l = 0; l < 2; l++) {
            int idx = tid + l*256;
            int row = idx >> 2;
            int fc  = (idx & 3) << 2;
            float4 xv = *(const float4*)(X + (size_t)(m0+row)*K + kt + fc);
            Xs[fc+0][row]=xv.x; Xs[fc+1][row]=xv.y; Xs[fc+2][row]=xv.z; Xs[fc+3][row]=xv.w;
            float4 wv = *(const float4*)(W + (size_t)(n0+row)*K + kt + fc);
            Ws[fc+0][row]=wv.x; Ws[fc+1][row]=wv.y; Ws[fc+2][row]=wv.z; Ws[fc+3][row]=wv.w;
        }
        __syncthreads();
        #pragma unroll
        for (int kk = 0; kk < 16; kk++) {
            float ar[8];
            *(float4*)(ar  ) = *(const float4*)&Xs[kk][rowc];
            *(float4*)(ar+4) = *(const float4*)&Xs[kk][rowc+4];
            ulonglong2 blo = *(const ulonglong2*)&Ws[kk][colc];
            ulonglong2 bhi = *(const ulonglong2*)&Ws[kk][colc+4];
            #pragma unroll
            for (int i = 0; i < 8; i++) {
                unsigned long long ad = dupf(ar[i]);
                fma2(acc2[i][0], ad, blo.x);
                fma2(acc2[i][1], ad, blo.y);
                fma2(acc2[i][2], ad, bhi.x);
                fma2(acc2[i][3], ad, bhi.y);
            }
        }
        __syncthreads();
    }

    #pragma unroll
    for (int i = 0; i < 8; i++) {
        float out[8];
        #pragma unroll
        for (int jp = 0; jp < 4; jp++) unpack2(acc2[i][jp], out[2*jp], out[2*jp+1]);
        #pragma unroll
        for (int j = 0; j < 8; j++) {
            float val = out[j] + (bias ? bias[n0+colc+j] : 0.0f);
            if (act == 1) val = 1.0f/(1.0f + expf(-val));
            Y[(size_t)(m0+rowc+i)*DIM + n0+colc+j] = val;
        }
    }
}

// ============================================================
// Sequential chain: 2 clusters x 8 CTAs, 2 BATCHES INTERLEAVED per
// cluster. While batch-0's blended vector transits the cluster,
// batch-1's step computes (and vice versa) -> DSMEM transit hidden.
// Per batch: identical R5/R6 broadcast-MAC structure + invariants.
// bl layout: [bb*2+p][DIM]; mbar: [bb*2+p]
// ============================================================
__global__ void __launch_bounds__(256, 1) __cluster_dims__(CLSZ, 1, 1)
chain_kernel(const float* __restrict__ q, const float* __restrict__ A,
             const float* __restrict__ G, const float* __restrict__ C,
             float* __restrict__ Sout)
{
    __shared__ __align__(16) float bl[2*BPC][DIM];        // [bb*2+p]
    __shared__ __align__(16) float part[BPC][64][4];
    __shared__ __align__(8)  unsigned long long mbar[2*BPC];

    int rank = blockIdx.x & (CLSZ-1);
    int cl   = blockIdx.x / CLSZ;     // cluster id 0..1
    int tid  = threadIdx.x;
    int w    = tid >> 5;
    int lane = tid & 31;
    int qw   = w >> 1;            // k-quarter (0..3), 128 k each
    int rh   = w & 1;             // row-half (0..1)
    int jl   = rh*32 + lane;      // output row within slice (0..63)
    int jg   = rank*64 + jl;      // global output row
    int kbase= qw*128;

    uint32_t bl_a = smem_u32(&bl[0][0]);
    uint32_t mb_a = smem_u32(&mbar[0]);
    uint32_t dmb  = mb_a - bl_a;

    if (tid == 0) {
        #pragma unroll
        for (int i = 0; i < 2*BPC; i++) mbar_init(mb_a + 8u*i, 1);
    }

    // remote bl base of every cluster CTA
    uint32_t rb[CLSZ];
    #pragma unroll
    for (int r = 0; r < CLSZ; r++)
        asm("mapa.shared::cluster.u32 %0, %1, %2;" : "=r"(rb[r]) : "r"(bl_a), "r"(r));

    // A slice in registers: row jg, k in [kbase,kbase+128) — shared by both batches
    unsigned long long a2[64];
    #pragma unroll
    for (int u = 0; u < 32; u++) {
        ulonglong2 av = *(const ulonglong2*)(A + (size_t)jg*DIM + kbase + 4*u);
        a2[2*u] = av.x; a2[2*u+1] = av.y;
    }

    const float *qb[BPC], *Gb[BPC], *Cb[BPC];
    float *Sb[BPC];
    #pragma unroll
    for (int bb = 0; bb < BPC; bb++) {
        int bi = cl*BPC + bb;
        qb[bb] = q    + (size_t)bi*SEQ*DIM;
        Gb[bb] = G    + (size_t)bi*SEQ*DIM;
        Cb[bb] = C    + (size_t)bi*SEQ*DIM;
        Sb[bb] = Sout + (size_t)bi*SEQ*DIM;
    }

    // arm buffer 0 of both batches, then cluster-wide publish
    if (tid == 0) {
        mbar_expect_tx(mb_a,        2048);   // bb0, buf0 (idx 0)
        mbar_expect_tx(mb_a + 16u,  2048);   // bb1, buf0 (idx 2)
    }
    CLUSTER_SYNC();   // barriers initialized + armed before any st.async

    // epilogue lanes: tid < 64, output row = tid
    int je = rank*64 + tid;           // valid when tid < 64
    float cc[BPC], cg[BPC], cq[BPC];
    #pragma unroll
    for (int bb = 0; bb < BPC; bb++) { cc[bb]=0.f; cg[bb]=0.f; cq[bb]=0.f; }

    if (tid < 64) {
        #pragma unroll
        for (int bb = 0; bb < BPC; bb++) {
            float g0 = Gb[bb][je], q0 = qb[bb][je];
            uint32_t bits = __float_as_uint((1.0f - g0) * q0);   // state_0 = 0
            uint32_t boff = (uint32_t)(bb*2)*2048u + (uint32_t)je*4u;
            uint32_t moff = dmb + (uint32_t)(bb*2)*8u;
            #pragma unroll
            for (int r = 0; r < CLSZ; r++)
                st_async_u32(rb[r] + boff, bits, rb[r] + moff);
            cc[bb] = Cb[bb][je]; cg[bb] = Gb[bb][DIM + je]; cq[bb] = qb[bb][DIM + je];
        }
    }

    for (int t = 0; t < SEQ; t++) {
        int p = t & 1;
        uint32_t ph = (t >> 1) & 1;

        // prefetch next operands (both batches) + arm next buffers BEFORE waiting
        float nc[BPC], ng[BPC], nq[BPC];
        #pragma unroll
        for (int bb = 0; bb < BPC; bb++) { nc[bb]=0.f; ng[bb]=0.f; nq[bb]=0.f; }
        if (tid < 64) {
            #pragma unroll
            for (int bb = 0; bb < BPC; bb++) {
                if (t+1 < SEQ) nc[bb] = Cb[bb][(size_t)(t+1)*DIM + je];
                if (t+2 < SEQ) { ng[bb] = Gb[bb][(size_t)(t+2)*DIM + je];
                                 nq[bb] = qb[bb][(size_t)(t+2)*DIM + je]; }
            }
        }
        if (tid == 0 && t+1 < SEQ) {
            mbar_expect_tx(mb_a + (uint32_t)(1-p)*8u,       2048);  // bb0
            mbar_expect_tx(mb_a + (uint32_t)(2+(1-p))*8u,   2048);  // bb1
        }

        // --- interleaved MAC phases: b1 computes while b0's data transits next step
        #pragma unroll
        for (int bb = 0; bb < BPC; bb++) {
            mbar_wait(mb_a + (uint32_t)(bb*2+p)*8u, ph);
            unsigned long long acc0 = 0ull, acc1 = 0ull;
            const float* blp = bl[bb*2+p] + kbase;
            #pragma unroll
            for (int u = 0; u < 32; u++) {
                ulonglong2 bv = *(const ulonglong2*)(blp + 4*u);
                fma2(acc0, a2[2*u],   bv.x);
                fma2(acc1, a2[2*u+1], bv.y);
            }
            float x0, x1, y0, y1;
            unpack2(acc0, x0, x1);
            unpack2(acc1, y0, y1);
            part[bb][jl][qw] = (x0 + x1) + (y0 + y1);
        }

        // all warps done reading both bl[p] buffers + partials published
        __syncthreads();

        if (tid < 64) {
            #pragma unroll
            for (int bb = 0; bb < BPC; bb++) {
                float4 pr = *(const float4*)&part[bb][tid][0];
                float acc = (pr.x + pr.y) + (pr.z + pr.w);
                float s = tanhf(acc + cc[bb]);
                Sb[bb][(size_t)t*DIM + je] = s;
                if (t+1 < SEQ) {
                    uint32_t bits = __float_as_uint(fmaf(cg[bb], s - cq[bb], cq[bb]));
                    uint32_t boff = (uint32_t)(bb*2+(1-p))*2048u + (uint32_t)je*4u;
                    uint32_t moff = dmb + (uint32_t)(bb*2+(1-p))*8u;
                    #pragma unroll
                    for (int r = 0; r < CLSZ; r++)
                        st_async_u32(rb[r] + boff, bits, rb[r] + moff);
                }
                cc[bb] = nc[bb]; cg[bb] = ng[bb]; cq[bb] = nq[bb];
            }
        }
    }
}

// ============================================================
// launch
// ============================================================
extern "C" void kernel_launch(void* const* d_in, const int* in_sizes, int n_in,
                              void* d_out, int out_size)
{
    const float* q     = (const float*)d_in[0];
    const float* k     = (const float*)d_in[1];
    const float* v     = (const float*)d_in[2];
    const float* A     = (const float*)d_in[3];
    const float* Bm    = (const float*)d_in[4];
    const float* gw    = (const float*)d_in[5];
    const float* gb    = (const float*)d_in[6];
    const float* ow    = (const float*)d_in[7];
    const float* ob    = (const float*)d_in[8];
    const float* decay = (const float*)d_in[9];
    float* out = (float*)d_out;

    float *R, *G, *C, *S;
    cudaGetSymbolAddress((void**)&R, g_R);
    cudaGetSymbolAddress((void**)&G, g_G);
    cudaGetSymbolAddress((void**)&C, g_C);
    cudaGetSymbolAddress((void**)&S, g_S);

    // 1) chunked linear scan for r
    scan_local <<<BATCH*NCHUNK*DIM/256, 256>>>(k, v, decay, 0);
    scan_prefix<<<BATCH*DIM/256,        256>>>(decay);
    scan_local <<<BATCH*NCHUNK*DIM/256, 256>>>(k, v, decay, 1);

    dim3 ggrid(DIM/128, ROWS/128);
    // 2) gates (sigmoid epilogue)
    gemm_kernel<<<ggrid, 256>>>(q, gw, gb, G, 1);
    // 3) C = R @ Bm^T
    gemm_kernel<<<ggrid, 256>>>(R, Bm, nullptr, C, 0);
    // 4) sequential recurrent chain: 2 clusters x 8 CTAs, 2 batches each
    chain_kernel<<<(BATCH/BPC)*CLSZ, 256>>>(q, A, G, C, S);
    // 5) out projection
    gemm_kernel<<<ggrid, 256>>>(S, ow, ob, out, 0);
}

// round 11
// speedup vs baseline: 1.0917x; 1.0917x over previous
#include <cuda_runtime.h>
#include <cstdint>
#include <math.h>

#define BATCH 4
#define SEQ   4096
#define DIM   512
#define ROWS  (BATCH*SEQ)   // 16384
#define NCHUNK 32
#define CHUNK  128          // SEQ / NCHUNK
#define CLSZ   8            // cluster size for chain

// ---- scratch (no cudaMalloc allowed) ----
__device__ float g_R[ROWS*DIM];
__device__ float g_G[ROWS*DIM];
__device__ float g_C[ROWS*DIM];
__device__ float g_S[ROWS*DIM];
__device__ float g_cf[BATCH*NCHUNK*DIM];
__device__ float g_cp[BATCH*NCHUNK*DIM];

// ---------------- helpers ----------------
__device__ __forceinline__ uint32_t smem_u32(const void* p) {
    return (uint32_t)__cvta_generic_to_shared(p);
}
__device__ __forceinline__ void fma2(unsigned long long& d, unsigned long long a, unsigned long long b) {
    asm("fma.rn.f32x2 %0, %1, %2, %0;" : "+l"(d) : "l"(a), "l"(b));
}
__device__ __forceinline__ unsigned long long dupf(float a) {
    unsigned long long r;
    asm("mov.b64 %0, {%1, %1};" : "=l"(r) : "f"(a));
    return r;
}
__device__ __forceinline__ void unpack2(unsigned long long v, float& lo, float& hi) {
    asm("mov.b64 {%0, %1}, %2;" : "=f"(lo), "=f"(hi) : "l"(v));
}
__device__ __forceinline__ void mbar_init(uint32_t addr, uint32_t cnt) {
    asm volatile("mbarrier.init.shared.b64 [%0], %1;" :: "r"(addr), "r"(cnt) : "memory");
}
__device__ __forceinline__ void mbar_expect_tx(uint32_t addr, uint32_t bytes) {
    asm volatile("mbarrier.arrive.expect_tx.shared.b64 _, [%0], %1;" :: "r"(addr), "r"(bytes) : "memory");
}
// DSMEM bulk copy: local SMEM -> cluster SMEM, complete_tx on dst barrier
__device__ __forceinline__ void bulk_copy_cluster(uint32_t rdst, uint32_t lsrc, uint32_t bytes, uint32_t rmbar) {
    asm volatile("cp.async.bulk.shared::cluster.shared::cta.mbarrier::complete_tx::bytes [%0], [%1], %2, [%3];"
                 :: "r"(rdst), "r"(lsrc), "r"(bytes), "r"(rmbar) : "memory");
}
__device__ __forceinline__ void fence_async_shared() {
    asm volatile("fence.proxy.async.shared::cta;" ::: "memory");
}
__device__ __forceinline__ void mbar_wait(uint32_t addr, uint32_t parity) {
    uint32_t done;
    asm volatile("{\n\t.reg .pred P;\n\t"
        "mbarrier.try_wait.parity.acquire.cta.shared::cta.b64 P, [%1], %2, 0x989680;\n\t"
        "selp.b32 %0, 1, 0, P;\n\t}"
        : "=r"(done) : "r"(addr), "r"(parity) : "memory");
    while (!done) {
        asm volatile("{\n\t.reg .pred P;\n\t"
            "mbarrier.try_wait.parity.acquire.cta.shared::cta.b64 P, [%1], %2, 0x989680;\n\t"
            "selp.b32 %0, 1, 0, P;\n\t}"
            : "=r"(done) : "r"(addr), "r"(parity) : "memory");
    }
}
#define CLUSTER_SYNC() do { \
    asm volatile("barrier.cluster.arrive.aligned;" ::: "memory"); \
    asm volatile("barrier.cluster.wait.aligned;"   ::: "memory"); } while (0)

// ============================================================
// Chunked linear scan for r
// ============================================================
__global__ void scan_local(const float* __restrict__ k, const float* __restrict__ v,
                           const float* __restrict__ decay, int store)
{
    int g = blockIdx.x*blockDim.x + threadIdx.x;
    int d = g % DIM;
    int c = (g / DIM) % NCHUNK;
    int b = g / (DIM*NCHUNK);
    float dec = decay[d >> 6];
    float r = store ? g_cp[g] : 0.0f;
    size_t base = ((size_t)b*SEQ + (size_t)c*CHUNK)*DIM + d;
    #pragma unroll 4
    for (int u = 0; u < CHUNK; u++) {
        size_t off = base + (size_t)u*DIM;
        r = fmaf(dec, r, k[off]*v[off]);
        if (store) g_R[off] = r;
    }
    if (!store) g_cf[g] = r;
}

__global__ void scan_prefix(const float* __restrict__ decay)
{
    int g = blockIdx.x*blockDim.x + threadIdx.x;
    int d = g % DIM;
    int b = g / DIM;
    float dec = decay[d >> 6];
    float dp = powf(dec, (float)CHUNK);
    float p = 0.0f;
    for (int c = 0; c < NCHUNK; c++) {
        int idx = (b*NCHUNK + c)*DIM + d;
        g_cp[idx] = p;
        p = g_cf[idx] + dp*p;
    }
}

// ============================================================
// GEMM: Y[M,512] = act(X[M,512] @ W[512,512]^T + bias), f32x2 inner
// ============================================================
__global__ __launch_bounds__(256)
void gemm_kernel(const float* __restrict__ X, const float* __restrict__ W,
                 const float* __restrict__ bias, float* __restrict__ Y, int act)
{
    __shared__ __align__(16) float Xs[16][132];
    __shared__ __align__(16) float Ws[16][132];
    const int K = DIM;
    int tid  = threadIdx.x;
    int m0   = blockIdx.y * 128;
    int n0   = blockIdx.x * 128;
    int rowc = (tid >> 4) << 3;
    int colc = (tid & 15) << 3;

    unsigned long long acc2[8][4];
    #pragma unroll
    for (int i = 0; i < 8; i++)
        #pragma unroll
        for (int j = 0; j < 4; j++) acc2[i][j] = 0ull;

    for (int kt = 0; kt < K; kt += 16) {
        #pragma unroll
        for (int l = 0; l < 2; l++) {
            int idx = tid + l*256;
            int row = idx >> 2;
            int fc  = (idx & 3) << 2;
            float4 xv = *(const float4*)(X + (size_t)(m0+row)*K + kt + fc);
            Xs[fc+0][row]=xv.x; Xs[fc+1][row]=xv.y; Xs[fc+2][row]=xv.z; Xs[fc+3][row]=xv.w;
            float4 wv = *(const float4*)(W + (size_t)(n0+row)*K + kt + fc);
            Ws[fc+0][row]=wv.x; Ws[fc+1][row]=wv.y; Ws[fc+2][row]=wv.z; Ws[fc+3][row]=wv.w;
        }
        __syncthreads();
        #pragma unroll
        for (int kk = 0; kk < 16; kk++) {
            float ar[8];
            *(float4*)(ar  ) = *(const float4*)&Xs[kk][rowc];
            *(float4*)(ar+4) = *(const float4*)&Xs[kk][rowc+4];
            ulonglong2 blo = *(const ulonglong2*)&Ws[kk][colc];
            ulonglong2 bhi = *(const ulonglong2*)&Ws[kk][colc+4];
            #pragma unroll
            for (int i = 0; i < 8; i++) {
                unsigned long long ad = dupf(ar[i]);
                fma2(acc2[i][0], ad, blo.x);
                fma2(acc2[i][1], ad, blo.y);
                fma2(acc2[i][2], ad, bhi.x);
                fma2(acc2[i][3], ad, bhi.y);
            }
        }
        __syncthreads();
    }

    #pragma unroll
    for (int i = 0; i < 8; i++) {
        float out[8];
        #pragma unroll
        for (int jp = 0; jp < 4; jp++) unpack2(acc2[i][jp], out[2*jp], out[2*jp+1]);
        #pragma unroll
        for (int j = 0; j < 8; j++) {
            float val = out[j] + (bias ? bias[n0+colc+j] : 0.0f);
            if (act == 1) val = 1.0f/(1.0f + expf(-val));
            Y[(size_t)(m0+rowc+i)*DIM + n0+colc+j] = val;
        }
    }
}

// ============================================================
// Sequential chain: 4 batches x 8-CTA clusters, 256 threads/CTA.
// Broadcast MAC layout (the proven 3980us structure) with the
// all-gather done by 8x 256B cluster bulk copies per step
// (8 mbarrier tx events/CTA/step instead of 512 scalar st.async).
// ============================================================
__global__ void __launch_bounds__(256, 1) __cluster_dims__(CLSZ, 1, 1)
chain_kernel(const float* __restrict__ q, const float* __restrict__ A,
             const float* __restrict__ G, const float* __restrict__ C,
             float* __restrict__ Sout)
{
    __shared__ __align__(16) float bl[2][DIM];            // double-buffered blended
    __shared__ __align__(16) float stage[2][64];          // outgoing slice, per dst buffer
    __shared__ __align__(16) float part[64][4];           // per-row partials
    __shared__ __align__(8)  unsigned long long mbar[2];  // full-barrier per buffer

    int rank = blockIdx.x & (CLSZ-1);
    int b    = blockIdx.x / CLSZ;
    int tid  = threadIdx.x;
    int w    = tid >> 5;
    int lane = tid & 31;
    int qw   = w >> 1;            // k-quarter (0..3), 128 k each
    int rh   = w & 1;             // row-half (0..1)
    int jl   = rh*32 + lane;      // output row within slice (0..63)
    int jg   = rank*64 + jl;      // global output row
    int kbase= qw*128;

    uint32_t bl_a = smem_u32(&bl[0][0]);
    uint32_t st_a = smem_u32(&stage[0][0]);
    uint32_t mb_a = smem_u32(&mbar[0]);
    uint32_t dmb  = mb_a - bl_a;

    if (tid == 0) { mbar_init(mb_a, 1); mbar_init(mb_a + 8, 1); }

    // remote bl base of every cluster CTA
    uint32_t rb[CLSZ];
    #pragma unroll
    for (int r = 0; r < CLSZ; r++)
        asm("mapa.shared::cluster.u32 %0, %1, %2;" : "=r"(rb[r]) : "r"(bl_a), "r"(r));

    // A slice in registers: row jg, k in [kbase, kbase+128)
    unsigned long long a2[64];
    #pragma unroll
    for (int u = 0; u < 32; u++) {
        ulonglong2 av = *(const ulonglong2*)(A + (size_t)jg*DIM + kbase + 4*u);
        a2[2*u] = av.x; a2[2*u+1] = av.y;
    }

    const float* qb = q    + (size_t)b*SEQ*DIM;
    const float* Gb = G    + (size_t)b*SEQ*DIM;
    const float* Cb = C    + (size_t)b*SEQ*DIM;
    float*       Sb = Sout + (size_t)b*SEQ*DIM;

    if (tid == 0) mbar_expect_tx(mb_a, 2048);   // arm buffer 0
    CLUSTER_SYNC();   // barriers initialized + armed cluster-wide before copies

    // epilogue lanes: tid < 64, output row = tid
    int je = rank*64 + tid;           // valid when tid < 64
    float cc = 0.f, cg = 0.f, cq = 0.f;
    if (tid < 64) {
        float g0 = Gb[je], q0 = qb[je];
        stage[0][tid] = (1.0f - g0) * q0;       // state_0 = 0; dst buffer 0
        cc = Cb[je]; cg = Gb[DIM + je]; cq = qb[DIM + je];
    }
    asm volatile("bar.sync 1, 64;" ::: "memory");   // warps 0-1: stage ready
    if (tid < CLSZ) {
        fence_async_shared();
        bulk_copy_cluster(rb[tid] + (uint32_t)rank*256u, st_a, 256u, rb[tid] + dmb);
    }

    for (int t = 0; t < SEQ; t++) {
        int p = t & 1;
        uint32_t ph = (t >> 1) & 1;

        // prefetch next operands + arm next buffer's barrier BEFORE waiting
        float nc = 0.f, ng = 0.f, nq = 0.f;
        if (tid < 64) {
            if (t+1 < SEQ) nc = Cb[(size_t)(t+1)*DIM + je];
            if (t+2 < SEQ) { ng = Gb[(size_t)(t+2)*DIM + je]; nq = qb[(size_t)(t+2)*DIM + je]; }
        }
        if (tid == 0 && t+1 < SEQ) mbar_expect_tx(mb_a + (uint32_t)(1-p)*8u, 2048);

        mbar_wait(mb_a + (uint32_t)p*8u, ph);

        // 128 MACs/thread; bl reads are warp-uniform -> broadcast LDS
        unsigned long long acc0 = 0ull, acc1 = 0ull;
        const float* blp = bl[p] + kbase;
        #pragma unroll
        for (int u = 0; u < 32; u++) {
            ulonglong2 bv = *(const ulonglong2*)(blp + 4*u);
            fma2(acc0, a2[2*u],   bv.x);
            fma2(acc1, a2[2*u+1], bv.y);
        }
        float x0, x1, y0, y1;
        unpack2(acc0, x0, x1);
        unpack2(acc1, y0, y1);
        part[jl][qw] = (x0 + x1) + (y0 + y1);

        // all warps done reading bl[p] + partials published
        __syncthreads();

        if (tid < 64) {
            float4 pr = *(const float4*)&part[tid][0];
            float acc = (pr.x + pr.y) + (pr.z + pr.w);
            float s = tanhf(acc + cc);
            Sb[(size_t)t*DIM + je] = s;
            if (t+1 < SEQ)
                stage[1-p][tid] = fmaf(cg, s - cq, cq);   // g*s + (1-g)*q
            cc = nc; cg = ng; cq = nq;
        }
        asm volatile("bar.sync 1, 64;" ::: "memory");     // warps 0-1: stage ready

        if (t+1 < SEQ && tid < CLSZ) {
            fence_async_shared();
            uint32_t boff = (uint32_t)(1-p)*2048u + (uint32_t)rank*256u;
            bulk_copy_cluster(rb[tid] + boff, st_a + (uint32_t)(1-p)*256u, 256u,
                              rb[tid] + dmb + (uint32_t)(1-p)*8u);
        }
    }
}

// ============================================================
// launch
// ============================================================
extern "C" void kernel_launch(void* const* d_in, const int* in_sizes, int n_in,
                              void* d_out, int out_size)
{
    const float* q     = (const float*)d_in[0];
    const float* k     = (const float*)d_in[1];
    const float* v     = (const float*)d_in[2];
    const float* A     = (const float*)d_in[3];
    const float* Bm    = (const float*)d_in[4];
    const float* gw    = (const float*)d_in[5];
    const float* gb    = (const float*)d_in[6];
    const float* ow    = (const float*)d_in[7];
    const float* ob    = (const float*)d_in[8];
    const float* decay = (const float*)d_in[9];
    float* out = (float*)d_out;

    float *R, *G, *C, *S;
    cudaGetSymbolAddress((void**)&R, g_R);
    cudaGetSymbolAddress((void**)&G, g_G);
    cudaGetSymbolAddress((void**)&C, g_C);
    cudaGetSymbolAddress((void**)&S, g_S);

    // 1) chunked linear scan for r
    scan_local <<<BATCH*NCHUNK*DIM/256, 256>>>(k, v, decay, 0);
    scan_prefix<<<BATCH*DIM/256,        256>>>(decay);
    scan_local <<<BATCH*NCHUNK*DIM/256, 256>>>(k, v, decay, 1);

    dim3 ggrid(DIM/128, ROWS/128);
    // 2) gates (sigmoid epilogue)
    gemm_kernel<<<ggrid, 256>>>(q, gw, gb, G, 1);
    // 3) C = R @ Bm^T
    gemm_kernel<<<ggrid, 256>>>(R, Bm, nullptr, C, 0);
    // 4) sequential recurrent chain (4 clusters of 8 CTAs)
    chain_kernel<<<BATCH*CLSZ, 256>>>(q, A, G, C, S);
    // 5) out projection
    gemm_kernel<<<ggrid, 256>>>(S, ow, ob, out, 0);
}

// round 12
// speedup vs baseline: 1.3398x; 1.2273x over previous
#include <cuda_runtime.h>
#include <cstdint>
#include <math.h>

#define BATCH 4
#define SEQ   4096
#define DIM   512
#define ROWS  (BATCH*SEQ)   // 16384
#define NCHUNK 32
#define CHUNK  128          // SEQ / NCHUNK
#define CLSZ   8            // cluster size for chain

// ---- scratch (no cudaMalloc allowed) ----
__device__ float g_R[ROWS*DIM];
__device__ float g_G[ROWS*DIM];
__device__ float g_C[ROWS*DIM];
__device__ float g_S[ROWS*DIM];
__device__ float g_cf[BATCH*NCHUNK*DIM];
__device__ float g_cp[BATCH*NCHUNK*DIM];

// ---------------- helpers ----------------
__device__ __forceinline__ uint32_t smem_u32(const void* p) {
    return (uint32_t)__cvta_generic_to_shared(p);
}
__device__ __forceinline__ void fma2(unsigned long long& d, unsigned long long a, unsigned long long b) {
    asm("fma.rn.f32x2 %0, %1, %2, %0;" : "+l"(d) : "l"(a), "l"(b));
}
__device__ __forceinline__ unsigned long long dupf(float a) {
    unsigned long long r;
    asm("mov.b64 %0, {%1, %1};" : "=l"(r) : "f"(a));
    return r;
}
__device__ __forceinline__ void unpack2(unsigned long long v, float& lo, float& hi) {
    asm("mov.b64 {%0, %1}, %2;" : "=f"(lo), "=f"(hi) : "l"(v));
}
__device__ __forceinline__ void mbar_init(uint32_t addr, uint32_t cnt) {
    asm volatile("mbarrier.init.shared.b64 [%0], %1;" :: "r"(addr), "r"(cnt) : "memory");
}
__device__ __forceinline__ void mbar_expect_tx(uint32_t addr, uint32_t bytes) {
    asm volatile("mbarrier.arrive.expect_tx.shared.b64 _, [%0], %1;" :: "r"(addr), "r"(bytes) : "memory");
}
// 8-byte async cluster store: HALVES the number of mbarrier tx-updates
__device__ __forceinline__ void st_async_u64(uint32_t raddr, unsigned long long val, uint32_t rmbar) {
    asm volatile("st.async.weak.shared::cluster.mbarrier::complete_tx::bytes.b64 [%0], %1, [%2];"
                 :: "r"(raddr), "l"(val), "r"(rmbar) : "memory");
}
__device__ __forceinline__ void mbar_wait(uint32_t addr, uint32_t parity) {
    uint32_t done;
    asm volatile("{\n\t.reg .pred P;\n\t"
        "mbarrier.try_wait.parity.acquire.cta.shared::cta.b64 P, [%1], %2, 0x989680;\n\t"
        "selp.b32 %0, 1, 0, P;\n\t}"
        : "=r"(done) : "r"(addr), "r"(parity) : "memory");
    while (!done) {
        asm volatile("{\n\t.reg .pred P;\n\t"
            "mbarrier.try_wait.parity.acquire.cta.shared::cta.b64 P, [%1], %2, 0x989680;\n\t"
            "selp.b32 %0, 1, 0, P;\n\t}"
            : "=r"(done) : "r"(addr), "r"(parity) : "memory");
    }
}
#define CLUSTER_SYNC() do { \
    asm volatile("barrier.cluster.arrive.aligned;" ::: "memory"); \
    asm volatile("barrier.cluster.wait.aligned;"   ::: "memory"); } while (0)

// ============================================================
// Chunked linear scan for r
// ============================================================
__global__ void scan_local(const float* __restrict__ k, const float* __restrict__ v,
                           const float* __restrict__ decay, int store)
{
    int g = blockIdx.x*blockDim.x + threadIdx.x;
    int d = g % DIM;
    int c = (g / DIM) % NCHUNK;
    int b = g / (DIM*NCHUNK);
    float dec = decay[d >> 6];
    float r = store ? g_cp[g] : 0.0f;
    size_t base = ((size_t)b*SEQ + (size_t)c*CHUNK)*DIM + d;
    #pragma unroll 4
    for (int u = 0; u < CHUNK; u++) {
        size_t off = base + (size_t)u*DIM;
        r = fmaf(dec, r, k[off]*v[off]);
        if (store) g_R[off] = r;
    }
    if (!store) g_cf[g] = r;
}

__global__ void scan_prefix(const float* __restrict__ decay)
{
    int g = blockIdx.x*blockDim.x + threadIdx.x;
    int d = g % DIM;
    int b = g / DIM;
    float dec = decay[d >> 6];
    float dp = powf(dec, (float)CHUNK);
    float p = 0.0f;
    for (int c = 0; c < NCHUNK; c++) {
        int idx = (b*NCHUNK + c)*DIM + d;
        g_cp[idx] = p;
        p = g_cf[idx] + dp*p;
    }
}

// ============================================================
// GEMM: Y[M,512] = act(X[M,512] @ W[512,512]^T + bias), f32x2 inner
// ============================================================
__global__ __launch_bounds__(256)
void gemm_kernel(const float* __restrict__ X, const float* __restrict__ W,
                 const float* __restrict__ bias, float* __restrict__ Y, int act)
{
    __shared__ __align__(16) float Xs[16][132];
    __shared__ __align__(16) float Ws[16][132];
    const int K = DIM;
    int tid  = threadIdx.x;
    int m0   = blockIdx.y * 128;
    int n0   = blockIdx.x * 128;
    int rowc = (tid >> 4) << 3;
    int colc = (tid & 15) << 3;

    unsigned long long acc2[8][4];
    #pragma unroll
    for (int i = 0; i < 8; i++)
        #pragma unroll
        for (int j = 0; j < 4; j++) acc2[i][j] = 0ull;

    for (int kt = 0; kt < K; kt += 16) {
        #pragma unroll
        for (int l = 0; l < 2; l++) {
            int idx = tid + l*256;
            int row = idx >> 2;
            int fc  = (idx & 3) << 2;
            float4 xv = *(const float4*)(X + (size_t)(m0+row)*K + kt + fc);
            Xs[fc+0][row]=xv.x; Xs[fc+1][row]=xv.y; Xs[fc+2][row]=xv.z; Xs[fc+3][row]=xv.w;
            float4 wv = *(const float4*)(W + (size_t)(n0+row)*K + kt + fc);
            Ws[fc+0][row]=wv.x; Ws[fc+1][row]=wv.y; Ws[fc+2][row]=wv.z; Ws[fc+3][row]=wv.w;
        }
        __syncthreads();
        #pragma unroll
        for (int kk = 0; kk < 16; kk++) {
            float ar[8];
            *(float4*)(ar  ) = *(const float4*)&Xs[kk][rowc];
            *(float4*)(ar+4) = *(const float4*)&Xs[kk][rowc+4];
            ulonglong2 blo = *(const ulonglong2*)&Ws[kk][colc];
            ulonglong2 bhi = *(const ulonglong2*)&Ws[kk][colc+4];
            #pragma unroll
            for (int i = 0; i < 8; i++) {
                unsigned long long ad = dupf(ar[i]);
                fma2(acc2[i][0], ad, blo.x);
                fma2(acc2[i][1], ad, blo.y);
                fma2(acc2[i][2], ad, bhi.x);
                fma2(acc2[i][3], ad, bhi.y);
            }
        }
        __syncthreads();
    }

    #pragma unroll
    for (int i = 0; i < 8; i++) {
        float out[8];
        #pragma unroll
        for (int jp = 0; jp < 4; jp++) unpack2(acc2[i][jp], out[2*jp], out[2*jp+1]);
        #pragma unroll
        for (int j = 0; j < 8; j++) {
            float val = out[j] + (bias ? bias[n0+colc+j] : 0.0f);
            if (act == 1) val = 1.0f/(1.0f + expf(-val));
            Y[(size_t)(m0+rowc+i)*DIM + n0+colc+j] = val;
        }
    }
}

// ============================================================
// Sequential chain: 4 batches x 8-CTA clusters, 256 threads/CTA.
// Broadcast MAC + half-split barriers (the 3980us R6 structure).
// NEW: epilogue lanes pair-pack neighbor rows (1 shfl) and even
// lanes issue st.async.b64 -> 256 barrier tx-updates/CTA/step
// instead of 512. Expected-tx byte counts unchanged.
// ============================================================
__global__ void __launch_bounds__(256, 1) __cluster_dims__(CLSZ, 1, 1)
chain_kernel(const float* __restrict__ q, const float* __restrict__ A,
             const float* __restrict__ G, const float* __restrict__ C,
             float* __restrict__ Sout)
{
    __shared__ __align__(16) float bl[2][DIM];            // double-buffered blended
    __shared__ __align__(16) float part[4][64];           // per-quarter partials
    __shared__ __align__(8)  unsigned long long mbar[4];  // [buf][half]

    int rank = blockIdx.x & (CLSZ-1);
    int b    = blockIdx.x / CLSZ;
    int tid  = threadIdx.x;
    int w    = tid >> 5;
    int lane = tid & 31;
    int qw   = w >> 1;            // k-quarter (0..3), 128 k each
    int rh   = w & 1;             // row-half (0..1)
    int jl   = rh*32 + lane;      // output row within slice (0..63)
    int jg   = rank*64 + jl;      // global output row
    int kbase= qw*128;
    int hw   = qw >> 1;           // half this warp CONSUMES (0 or 1)
    int myh  = rank >> 2;         // half this CTA PRODUCES

    uint32_t bl_a = smem_u32(&bl[0][0]);
    uint32_t mb_a = smem_u32(&mbar[0]);
    uint32_t dmb  = mb_a - bl_a;

    if (tid == 0) {
        mbar_init(mb_a,      1);  // buf0 half0
        mbar_init(mb_a + 8,  1);  // buf0 half1
        mbar_init(mb_a + 16, 1);  // buf1 half0
        mbar_init(mb_a + 24, 1);  // buf1 half1
    }

    // remote bl base of every cluster CTA
    uint32_t rb[CLSZ];
    #pragma unroll
    for (int r = 0; r < CLSZ; r++)
        asm("mapa.shared::cluster.u32 %0, %1, %2;" : "=r"(rb[r]) : "r"(bl_a), "r"(r));

    // A slice in registers: row jg, k in [kbase, kbase+128)
    unsigned long long a2[64];
    #pragma unroll
    for (int u = 0; u < 32; u++) {
        ulonglong2 av = *(const ulonglong2*)(A + (size_t)jg*DIM + kbase + 4*u);
        a2[2*u] = av.x; a2[2*u+1] = av.y;
    }

    const float* qb = q    + (size_t)b*SEQ*DIM;
    const float* Gb = G    + (size_t)b*SEQ*DIM;
    const float* Cb = C    + (size_t)b*SEQ*DIM;
    float*       Sb = Sout + (size_t)b*SEQ*DIM;

    CLUSTER_SYNC();   // barriers initialized cluster-wide before any st.async

    // epilogue lanes: tid < 64 (warps 0-1), output row = tid
    int je = rank*64 + tid;           // valid when tid < 64
    float cc = 0.f, cg = 0.f, cq = 0.f;
    if (tid == 0) {                   // arm both halves of buffer 0
        mbar_expect_tx(mb_a,     1024);
        mbar_expect_tx(mb_a + 8, 1024);
    }
    if (tid < 64) {
        float g0 = Gb[je], q0 = qb[je];
        uint32_t bits = __float_as_uint((1.0f - g0) * q0);   // state_0 = 0
        uint32_t obits = __shfl_xor_sync(0xffffffffu, bits, 1);
        if ((tid & 1) == 0) {
            unsigned long long pk = (unsigned long long)bits |
                                    ((unsigned long long)obits << 32);
            uint32_t moff = dmb + (uint32_t)myh*8u;          // buf0, half myh
            #pragma unroll
            for (int r = 0; r < CLSZ; r++)
                st_async_u64(rb[r] + (uint32_t)je*4u, pk, rb[r] + moff);
        }
        cc = Cb[je]; cg = Gb[DIM + je]; cq = qb[DIM + je];
    }

    for (int t = 0; t < SEQ; t++) {
        int p = t & 1;
        uint32_t ph = (t >> 1) & 1;

        // prefetch next operands + arm next buffer's barriers BEFORE waiting
        float nc = 0.f, ng = 0.f, nq = 0.f;
        if (tid < 64) {
            if (t+1 < SEQ) nc = Cb[(size_t)(t+1)*DIM + je];
            if (t+2 < SEQ) { ng = Gb[(size_t)(t+2)*DIM + je]; nq = qb[(size_t)(t+2)*DIM + je]; }
        }
        if (tid == 0 && t+1 < SEQ) {
            mbar_expect_tx(mb_a + (uint32_t)(1-p)*16u,      1024);
            mbar_expect_tx(mb_a + (uint32_t)(1-p)*16u + 8u, 1024);
        }

        // wait only for the half this warp consumes
        mbar_wait(mb_a + (uint32_t)p*16u + (uint32_t)hw*8u, ph);

        // 128 MACs/thread; bl reads are warp-uniform -> broadcast LDS
        unsigned long long acc0 = 0ull, acc1 = 0ull;
        const float* blp = bl[p] + kbase;
        #pragma unroll
        for (int u = 0; u < 32; u++) {
            ulonglong2 bv = *(const ulonglong2*)(blp + 4*u);
            fma2(acc0, a2[2*u],   bv.x);
            fma2(acc1, a2[2*u+1], bv.y);
        }
        float x0, x1, y0, y1;
        unpack2(acc0, x0, x1);
        unpack2(acc1, y0, y1);
        part[qw][jl] = (x0 + x1) + (y0 + y1);

        // all warps done reading bl[p] + partials published
        __syncthreads();

        if (tid < 64) {
            float acc = (part[0][tid] + part[1][tid]) + (part[2][tid] + part[3][tid]);
            float s = tanhf(acc + cc);
            Sb[(size_t)t*DIM + je] = s;
            uint32_t bits = __float_as_uint(fmaf(cg, s - cq, cq)); // g*s+(1-g)*q
            uint32_t obits = __shfl_xor_sync(0xffffffffu, bits, 1);
            if (t+1 < SEQ && (tid & 1) == 0) {
                unsigned long long pk = (unsigned long long)bits |
                                        ((unsigned long long)obits << 32);
                uint32_t boff = (uint32_t)(1-p)*2048u + (uint32_t)je*4u;
                uint32_t moff = dmb + (uint32_t)(1-p)*16u + (uint32_t)myh*8u;
                #pragma unroll
                for (int r = 0; r < CLSZ; r++)
                    st_async_u64(rb[r] + boff, pk, rb[r] + moff);
            }
            cc = nc; cg = ng; cq = nq;
        }
    }
}

// ============================================================
// launch
// ============================================================
extern "C" void kernel_launch(void* const* d_in, const int* in_sizes, int n_in,
                              void* d_out, int out_size)
{
    const float* q     = (const float*)d_in[0];
    const float* k     = (const float*)d_in[1];
    const float* v     = (const float*)d_in[2];
    const float* A     = (const float*)d_in[3];
    const float* Bm    = (const float*)d_in[4];
    const float* gw    = (const float*)d_in[5];
    const float* gb    = (const float*)d_in[6];
    const float* ow    = (const float*)d_in[7];
    const float* ob    = (const float*)d_in[8];
    const float* decay = (const float*)d_in[9];
    float* out = (float*)d_out;

    float *R, *G, *C, *S;
    cudaGetSymbolAddress((void**)&R, g_R);
    cudaGetSymbolAddress((void**)&G, g_G);
    cudaGetSymbolAddress((void**)&C, g_C);
    cudaGetSymbolAddress((void**)&S, g_S);

    // 1) chunked linear scan for r
    scan_local <<<BATCH*NCHUNK*DIM/256, 256>>>(k, v, decay, 0);
    scan_prefix<<<BATCH*DIM/256,        256>>>(decay);
    scan_local <<<BATCH*NCHUNK*DIM/256, 256>>>(k, v, decay, 1);

    dim3 ggrid(DIM/128, ROWS/128);
    // 2) gates (sigmoid epilogue)
    gemm_kernel<<<ggrid, 256>>>(q, gw, gb, G, 1);
    // 3) C = R @ Bm^T
    gemm_kernel<<<ggrid, 256>>>(R, Bm, nullptr, C, 0);
    // 4) sequential recurrent chain (4 clusters of 8 CTAs)
    chain_kernel<<<BATCH*CLSZ, 256>>>(q, A, G, C, S);
    // 5) out projection
    gemm_kernel<<<ggrid, 256>>>(S, ow, ob, out, 0);
}

// round 13
// speedup vs baseline: 1.4038x; 1.0477x over previous
#include <cuda_runtime.h>
#include <cstdint>
#include <math.h>

#define BATCH 4
#define SEQ   4096
#define DIM   512
#define ROWS  (BATCH*SEQ)   // 16384
#define NCHUNK 32
#define CHUNK  128          // SEQ / NCHUNK
#define CLSZ   8            // cluster size for chain

// ---- scratch (no cudaMalloc allowed) ----
__device__ float g_R[ROWS*DIM];
__device__ float g_G[ROWS*DIM];
__device__ float g_C[ROWS*DIM];
__device__ float g_S[ROWS*DIM];
__device__ float g_cf[BATCH*NCHUNK*DIM];
__device__ float g_cp[BATCH*NCHUNK*DIM];

// ---------------- helpers ----------------
__device__ __forceinline__ uint32_t smem_u32(const void* p) {
    return (uint32_t)__cvta_generic_to_shared(p);
}
__device__ __forceinline__ void fma2(unsigned long long& d, unsigned long long a, unsigned long long b) {
    asm("fma.rn.f32x2 %0, %1, %2, %0;" : "+l"(d) : "l"(a), "l"(b));
}
__device__ __forceinline__ unsigned long long dupf(float a) {
    unsigned long long r;
    asm("mov.b64 %0, {%1, %1};" : "=l"(r) : "f"(a));
    return r;
}
__device__ __forceinline__ void unpack2(unsigned long long v, float& lo, float& hi) {
    asm("mov.b64 {%0, %1}, %2;" : "=f"(lo), "=f"(hi) : "l"(v));
}
__device__ __forceinline__ void mbar_init(uint32_t addr, uint32_t cnt) {
    asm volatile("mbarrier.init.shared.b64 [%0], %1;" :: "r"(addr), "r"(cnt) : "memory");
}
__device__ __forceinline__ void mbar_expect_tx(uint32_t addr, uint32_t bytes) {
    asm volatile("mbarrier.arrive.expect_tx.shared.b64 _, [%0], %1;" :: "r"(addr), "r"(bytes) : "memory");
}
__device__ __forceinline__ void st_async_u32(uint32_t raddr, uint32_t val, uint32_t rmbar) {
    asm volatile("st.async.weak.shared::cluster.mbarrier::complete_tx::bytes.b32 [%0], %1, [%2];"
                 :: "r"(raddr), "r"(val), "r"(rmbar) : "memory");
}
__device__ __forceinline__ void mbar_wait(uint32_t addr, uint32_t parity) {
    uint32_t done;
    asm volatile("{\n\t.reg .pred P;\n\t"
        "mbarrier.try_wait.parity.acquire.cta.shared::cta.b64 P, [%1], %2, 0x989680;\n\t"
        "selp.b32 %0, 1, 0, P;\n\t}"
        : "=r"(done) : "r"(addr), "r"(parity) : "memory");
    while (!done) {
        asm volatile("{\n\t.reg .pred P;\n\t"
            "mbarrier.try_wait.parity.acquire.cta.shared::cta.b64 P, [%1], %2, 0x989680;\n\t"
            "selp.b32 %0, 1, 0, P;\n\t}"
            : "=r"(done) : "r"(addr), "r"(parity) : "memory");
    }
}
#define CLUSTER_SYNC() do { \
    asm volatile("barrier.cluster.arrive.aligned;" ::: "memory"); \
    asm volatile("barrier.cluster.wait.aligned;"   ::: "memory"); } while (0)

// ============================================================
// Chunked linear scan for r
// ============================================================
__global__ void scan_local(const float* __restrict__ k, const float* __restrict__ v,
                           const float* __restrict__ decay, int store)
{
    int g = blockIdx.x*blockDim.x + threadIdx.x;
    int d = g % DIM;
    int c = (g / DIM) % NCHUNK;
    int b = g / (DIM*NCHUNK);
    float dec = decay[d >> 6];
    float r = store ? g_cp[g] : 0.0f;
    size_t base = ((size_t)b*SEQ + (size_t)c*CHUNK)*DIM + d;
    #pragma unroll 4
    for (int u = 0; u < CHUNK; u++) {
        size_t off = base + (size_t)u*DIM;
        r = fmaf(dec, r, k[off]*v[off]);
        if (store) g_R[off] = r;
    }
    if (!store) g_cf[g] = r;
}

__global__ void scan_prefix(const float* __restrict__ decay)
{
    int g = blockIdx.x*blockDim.x + threadIdx.x;
    int d = g % DIM;
    int b = g / DIM;
    float dec = decay[d >> 6];
    float dp = powf(dec, (float)CHUNK);
    float p = 0.0f;
    for (int c = 0; c < NCHUNK; c++) {
        int idx = (b*NCHUNK + c)*DIM + d;
        g_cp[idx] = p;
        p = g_cf[idx] + dp*p;
    }
}

// ============================================================
// GEMM: Y[M,512] = act(X[M,512] @ W[512,512]^T + bias)
// f32x2 inner, DOUBLE-BUFFERED smem (1 barrier per k-iter)
// ============================================================
__global__ __launch_bounds__(256)
void gemm_kernel(const float* __restrict__ X, const float* __restrict__ W,
                 const float* __restrict__ bias, float* __restrict__ Y, int act)
{
    __shared__ __align__(16) float Xs[2][16][132];
    __shared__ __align__(16) float Ws[2][16][132];
    const int K = DIM;
    int tid  = threadIdx.x;
    int m0   = blockIdx.y * 128;
    int n0   = blockIdx.x * 128;
    int rowc = (tid >> 4) << 3;
    int colc = (tid & 15) << 3;

    // load indices (fixed per thread)
    int lrow0 = tid >> 2,        lfc0 = (tid & 3) << 2;
    int lrow1 = (tid+256) >> 2,  lfc1 = ((tid+256) & 3) << 2;

    unsigned long long acc2[8][4];
    #pragma unroll
    for (int i = 0; i < 8; i++)
        #pragma unroll
        for (int j = 0; j < 4; j++) acc2[i][j] = 0ull;

    // preload kt=0 into buffer 0
    {
        float4 xv = *(const float4*)(X + (size_t)(m0+lrow0)*K + lfc0);
        Xs[0][lfc0+0][lrow0]=xv.x; Xs[0][lfc0+1][lrow0]=xv.y; Xs[0][lfc0+2][lrow0]=xv.z; Xs[0][lfc0+3][lrow0]=xv.w;
        float4 wv = *(const float4*)(W + (size_t)(n0+lrow0)*K + lfc0);
        Ws[0][lfc0+0][lrow0]=wv.x; Ws[0][lfc0+1][lrow0]=wv.y; Ws[0][lfc0+2][lrow0]=wv.z; Ws[0][lfc0+3][lrow0]=wv.w;
        float4 xv1 = *(const float4*)(X + (size_t)(m0+lrow1)*K + lfc1);
        Xs[0][lfc1+0][lrow1]=xv1.x; Xs[0][lfc1+1][lrow1]=xv1.y; Xs[0][lfc1+2][lrow1]=xv1.z; Xs[0][lfc1+3][lrow1]=xv1.w;
        float4 wv1 = *(const float4*)(W + (size_t)(n0+lrow1)*K + lfc1);
        Ws[0][lfc1+0][lrow1]=wv1.x; Ws[0][lfc1+1][lrow1]=wv1.y; Ws[0][lfc1+2][lrow1]=wv1.z; Ws[0][lfc1+3][lrow1]=wv1.w;
    }
    __syncthreads();

    for (int it = 0; it < K/16; it++) {
        int cur = it & 1, nxt = 1 - cur;
        // issue next tile's loads first (hidden under compute)
        if (it + 1 < K/16) {
            int kt = (it+1)*16;
            float4 xv = *(const float4*)(X + (size_t)(m0+lrow0)*K + kt + lfc0);
            Xs[nxt][lfc0+0][lrow0]=xv.x; Xs[nxt][lfc0+1][lrow0]=xv.y; Xs[nxt][lfc0+2][lrow0]=xv.z; Xs[nxt][lfc0+3][lrow0]=xv.w;
            float4 wv = *(const float4*)(W + (size_t)(n0+lrow0)*K + kt + lfc0);
            Ws[nxt][lfc0+0][lrow0]=wv.x; Ws[nxt][lfc0+1][lrow0]=wv.y; Ws[nxt][lfc0+2][lrow0]=wv.z; Ws[nxt][lfc0+3][lrow0]=wv.w;
            float4 xv1 = *(const float4*)(X + (size_t)(m0+lrow1)*K + kt + lfc1);
            Xs[nxt][lfc1+0][lrow1]=xv1.x; Xs[nxt][lfc1+1][lrow1]=xv1.y; Xs[nxt][lfc1+2][lrow1]=xv1.z; Xs[nxt][lfc1+3][lrow1]=xv1.w;
            float4 wv1 = *(const float4*)(W + (size_t)(n0+lrow1)*K + kt + lfc1);
            Ws[nxt][lfc1+0][lrow1]=wv1.x; Ws[nxt][lfc1+1][lrow1]=wv1.y; Ws[nxt][lfc1+2][lrow1]=wv1.z; Ws[nxt][lfc1+3][lrow1]=wv1.w;
        }
        #pragma unroll
        for (int kk = 0; kk < 16; kk++) {
            float ar[8];
            *(float4*)(ar  ) = *(const float4*)&Xs[cur][kk][rowc];
            *(float4*)(ar+4) = *(const float4*)&Xs[cur][kk][rowc+4];
            ulonglong2 blo = *(const ulonglong2*)&Ws[cur][kk][colc];
            ulonglong2 bhi = *(const ulonglong2*)&Ws[cur][kk][colc+4];
            #pragma unroll
            for (int i = 0; i < 8; i++) {
                unsigned long long ad = dupf(ar[i]);
                fma2(acc2[i][0], ad, blo.x);
                fma2(acc2[i][1], ad, blo.y);
                fma2(acc2[i][2], ad, bhi.x);
                fma2(acc2[i][3], ad, bhi.y);
            }
        }
        __syncthreads();   // next buffer fully written + current fully read
    }

    #pragma unroll
    for (int i = 0; i < 8; i++) {
        float out[8];
        #pragma unroll
        for (int jp = 0; jp < 4; jp++) unpack2(acc2[i][jp], out[2*jp], out[2*jp+1]);
        #pragma unroll
        for (int j = 0; j < 8; j++) {
            float val = out[j] + (bias ? bias[n0+colc+j] : 0.0f);
            if (act == 1) val = 1.0f/(1.0f + expf(-val));
            Y[(size_t)(m0+rowc+i)*DIM + n0+colc+j] = val;
        }
    }
}

// ============================================================
// Sequential chain: the proven 3980us structure (R6), unchanged.
// ============================================================
__global__ void __launch_bounds__(256, 1) __cluster_dims__(CLSZ, 1, 1)
chain_kernel(const float* __restrict__ q, const float* __restrict__ A,
             const float* __restrict__ G, const float* __restrict__ C,
             float* __restrict__ Sout)
{
    __shared__ __align__(16) float bl[2][DIM];
    __shared__ __align__(16) float part[4][64];
    __shared__ __align__(8)  unsigned long long mbar[4];  // [buf][half]

    int rank = blockIdx.x & (CLSZ-1);
    int b    = blockIdx.x / CLSZ;
    int tid  = threadIdx.x;
    int w    = tid >> 5;
    int lane = tid & 31;
    int qw   = w >> 1;
    int rh   = w & 1;
    int jl   = rh*32 + lane;
    int jg   = rank*64 + jl;
    int kbase= qw*128;
    int hw   = qw >> 1;
    int myh  = rank >> 2;

    uint32_t bl_a = smem_u32(&bl[0][0]);
    uint32_t mb_a = smem_u32(&mbar[0]);
    uint32_t dmb  = mb_a - bl_a;

    if (tid == 0) {
        mbar_init(mb_a,      1);
        mbar_init(mb_a + 8,  1);
        mbar_init(mb_a + 16, 1);
        mbar_init(mb_a + 24, 1);
    }

    uint32_t rb[CLSZ];
    #pragma unroll
    for (int r = 0; r < CLSZ; r++)
        asm("mapa.shared::cluster.u32 %0, %1, %2;" : "=r"(rb[r]) : "r"(bl_a), "r"(r));

    unsigned long long a2[64];
    #pragma unroll
    for (int u = 0; u < 32; u++) {
        ulonglong2 av = *(const ulonglong2*)(A + (size_t)jg*DIM + kbase + 4*u);
        a2[2*u] = av.x; a2[2*u+1] = av.y;
    }

    const float* qb = q    + (size_t)b*SEQ*DIM;
    const float* Gb = G    + (size_t)b*SEQ*DIM;
    const float* Cb = C    + (size_t)b*SEQ*DIM;
    float*       Sb = Sout + (size_t)b*SEQ*DIM;

    CLUSTER_SYNC();

    int je = rank*64 + tid;
    float cc = 0.f, cg = 0.f, cq = 0.f;
    if (tid == 0) {
        mbar_expect_tx(mb_a,     1024);
        mbar_expect_tx(mb_a + 8, 1024);
    }
    if (tid < 64) {
        float g0 = Gb[je], q0 = qb[je];
        uint32_t bits = __float_as_uint((1.0f - g0) * q0);
        uint32_t moff = dmb + (uint32_t)myh*8u;
        #pragma unroll
        for (int r = 0; r < CLSZ; r++)
            st_async_u32(rb[r] + (uint32_t)je*4u, bits, rb[r] + moff);
        cc = Cb[je]; cg = Gb[DIM + je]; cq = qb[DIM + je];
    }

    for (int t = 0; t < SEQ; t++) {
        int p = t & 1;
        uint32_t ph = (t >> 1) & 1;

        float nc = 0.f, ng = 0.f, nq = 0.f;
        if (tid < 64) {
            if (t+1 < SEQ) nc = Cb[(size_t)(t+1)*DIM + je];
            if (t+2 < SEQ) { ng = Gb[(size_t)(t+2)*DIM + je]; nq = qb[(size_t)(t+2)*DIM + je]; }
        }
        if (tid == 0 && t+1 < SEQ) {
            mbar_expect_tx(mb_a + (uint32_t)(1-p)*16u,      1024);
            mbar_expect_tx(mb_a + (uint32_t)(1-p)*16u + 8u, 1024);
        }

        mbar_wait(mb_a + (uint32_t)p*16u + (uint32_t)hw*8u, ph);

        unsigned long long acc0 = 0ull, acc1 = 0ull;
        const float* blp = bl[p] + kbase;
        #pragma unroll
        for (int u = 0; u < 32; u++) {
            ulonglong2 bv = *(const ulonglong2*)(blp + 4*u);
            fma2(acc0, a2[2*u],   bv.x);
            fma2(acc1, a2[2*u+1], bv.y);
        }
        float x0, x1, y0, y1;
        unpack2(acc0, x0, x1);
        unpack2(acc1, y0, y1);
        part[qw][jl] = (x0 + x1) + (y0 + y1);

        __syncthreads();

        if (tid < 64) {
            float acc = (part[0][tid] + part[1][tid]) + (part[2][tid] + part[3][tid]);
            float s = tanhf(acc + cc);
            Sb[(size_t)t*DIM + je] = s;
            if (t+1 < SEQ) {
                uint32_t bits = __float_as_uint(fmaf(cg, s - cq, cq));
                uint32_t boff = (uint32_t)(1-p)*2048u + (uint32_t)je*4u;
                uint32_t moff = dmb + (uint32_t)(1-p)*16u + (uint32_t)myh*8u;
                #pragma unroll
                for (int r = 0; r < CLSZ; r++)
                    st_async_u32(rb[r] + boff, bits, rb[r] + moff);
            }
            cc = nc; cg = ng; cq = nq;
        }
    }
}

// ============================================================
// launch — fork-join stream overlap inside graph capture:
//   s0 (caller stream): scans -> C-gemm
//   s1:                 G-gemm   (independent of scans)
//   join -> chain -> out-gemm
// ============================================================
extern "C" void kernel_launch(void* const* d_in, const int* in_sizes, int n_in,
                              void* d_out, int out_size)
{
    const float* q     = (const float*)d_in[0];
    const float* k     = (const float*)d_in[1];
    const float* v     = (const float*)d_in[2];
    const float* A     = (const float*)d_in[3];
    const float* Bm    = (const float*)d_in[4];
    const float* gw    = (const float*)d_in[5];
    const float* gb    = (const float*)d_in[6];
    const float* ow    = (const float*)d_in[7];
    const float* ob    = (const float*)d_in[8];
    const float* decay = (const float*)d_in[9];
    float* out = (float*)d_out;

    float *R, *G, *C, *S;
    cudaGetSymbolAddress((void**)&R, g_R);
    cudaGetSymbolAddress((void**)&G, g_G);
    cudaGetSymbolAddress((void**)&C, g_C);
    cudaGetSymbolAddress((void**)&S, g_S);

    // one-time resources (not allocations of device memory)
    static cudaStream_t s1 = nullptr;
    static cudaEvent_t  eFork = nullptr, eJoin = nullptr;
    if (!s1) {
        cudaStreamCreateWithFlags(&s1, cudaStreamNonBlocking);
        cudaEventCreateWithFlags(&eFork, cudaEventDisableTiming);
        cudaEventCreateWithFlags(&eJoin, cudaEventDisableTiming);
    }

    dim3 ggrid(DIM/128, ROWS/128);   // (4, 128)

    // fork: s1 <- s0
    cudaEventRecord(eFork, 0);
    cudaStreamWaitEvent(s1, eFork, 0);

    // s1: gates GEMM (depends only on q)
    gemm_kernel<<<ggrid, 256, 0, s1>>>(q, gw, gb, G, 1);
    cudaEventRecord(eJoin, s1);

    // s0: scans -> C GEMM
    scan_local <<<BATCH*NCHUNK*DIM/256, 256>>>(k, v, decay, 0);
    scan_prefix<<<BATCH*DIM/256,        256>>>(decay);
    scan_local <<<BATCH*NCHUNK*DIM/256, 256>>>(k, v, decay, 1);
    gemm_kernel<<<ggrid, 256>>>(R, Bm, nullptr, C, 0);

    // join: s0 waits for G
    cudaStreamWaitEvent(0, eJoin, 0);

    // chain + out projection
    chain_kernel<<<BATCH*CLSZ, 256>>>(q, A, G, C, S);
    gemm_kernel<<<ggrid, 256>>>(S, ow, ob, out, 0);
}